// round 9
// baseline (speedup 1.0000x reference)
#include <cuda_runtime.h>
#include <cuda_bf16.h>
#include <math.h>
#include <stdint.h>

// Problem constants
#define NV 50000     // vocab
#define NE 300       // embed dim
#define NF 300       // filters
#define NFS 3        // filter size
#define NSENT 1024   // sentences per doc
#define SLEN 128     // sentence length
#define QLEN 32      // question length

// ---------------------------------------------------------------------------
// Device-global scratch — TOTAL ~231KB. (The harness's memory guard charges
// module memory in 128MiB arena chunks at lazy module load inside its
// checkpoint bracket; every MB-scale table tripped it. All large
// intermediates now live in shared memory inside one fused kernel.)
__device__ float g_B2[NE * 128];     // 153.6KB [e][c]: c<32 = q_emb; 32+32k+q = U_k[q]
__device__ float g_qemb[QLEN * NE];  // 38.4KB
__device__ float g_qconv[QLEN * NF]; // 38.4KB
__device__ float g_invq[64];         // [0..31]=1/|q_emb|, [32..63]=1/|q_conv|

// ---------------------------------------------------------------------------
// K1a: gather q_emb, fill B2 cols 0..31, compute 1/|q_emb|
__global__ void k_prep_q(const float* __restrict__ embeds, const int* __restrict__ question) {
    int q = blockIdx.x;
    int tid = threadIdx.x;
    int tok = question[q];
    const float* src = embeds + (size_t)tok * NE;
    float ss = 0.f;
    for (int e = tid; e < NE; e += 128) {
        float v = src[e];
        g_qemb[q * NE + e] = v;
        g_B2[e * 128 + q] = v;
        ss += v * v;
    }
    __shared__ float red[128];
    red[tid] = ss;
    __syncthreads();
    for (int o = 64; o > 0; o >>= 1) {
        if (tid < o) red[tid] += red[tid + o];
        __syncthreads();
    }
    if (tid == 0) g_invq[q] = 1.0f / sqrtf(red[0]);
}

// K1b: q_conv[q,f] = sum_k sum_e q_emb[q+k,e] * W[f,k,e]   (zero-pad past QLEN)
__global__ void k_qconv(const float* __restrict__ filters) {
    int q = blockIdx.x;
    int f = blockIdx.y * 128 + threadIdx.x;
    if (f >= NF) return;
    float acc = 0.f;
    for (int k = 0; k < NFS; k++) {
        if (q + k >= QLEN) break;
        const float* w = filters + (size_t)f * 900 + k * 300;
        const float* x = g_qemb + (q + k) * NE;
        #pragma unroll 4
        for (int e = 0; e < NE; e++) acc += x[e] * w[e];
    }
    g_qconv[q * NF + f] = acc;
}

// K1c: 1/|q_conv[q]|
__global__ void k_qnorm(void) {
    int q = blockIdx.x;
    int tid = threadIdx.x;
    float ss = 0.f;
    for (int f = tid; f < NF; f += 128) {
        float v = g_qconv[q * NF + f];
        ss += v * v;
    }
    __shared__ float red[128];
    red[tid] = ss;
    __syncthreads();
    for (int o = 64; o > 0; o >>= 1) {
        if (tid < o) red[tid] += red[tid + o];
        __syncthreads();
    }
    if (tid == 0) g_invq[32 + q] = 1.0f / sqrtf(red[0]);
}

// K1d: U[k,q,e] = sum_f W[f,k,e]*q_conv[q,f]  -> B2 col 32 + k*32 + q
__global__ void k_buildU(const float* __restrict__ filters) {
    int c = blockIdx.x;            // 0..95 ; k = c>>5, q = c&31
    int k = c >> 5, q = c & 31;
    for (int e = threadIdx.x; e < NE; e += 128) {
        float acc = 0.f;
        for (int f = 0; f < NF; f++)
            acc += filters[(size_t)f * 900 + k * 300 + e] * g_qconv[q * NF + f];
        g_B2[e * 128 + 32 + c] = acc;
    }
}

// ---------------------------------------------------------------------------
// Warp-cooperative top-5 over 128 values: returns max and mean-of-top-5.
__device__ __forceinline__ void top5(const float* __restrict__ row, int lane,
                                     float& mx, float& mean5) {
    float v[4];
    #pragma unroll
    for (int j = 0; j < 4; j++) v[j] = row[lane + 32 * j];
    float summ = 0.f;
    mx = 0.f;
    #pragma unroll
    for (int r = 0; r < 5; r++) {
        float bv = v[0];
        int bj = 0;
        #pragma unroll
        for (int j = 1; j < 4; j++)
            if (v[j] > bv) { bv = v[j]; bj = j; }
        float cv = bv;
        int cid = (lane << 2) | bj;
        #pragma unroll
        for (int o = 16; o > 0; o >>= 1) {
            float ov = __shfl_down_sync(0xffffffffu, cv, o);
            int oi = __shfl_down_sync(0xffffffffu, cid, o);
            if (ov > cv || (ov == cv && oi < cid)) { cv = ov; cid = oi; }
        }
        cv = __shfl_sync(0xffffffffu, cv, 0);
        cid = __shfl_sync(0xffffffffu, cid, 0);
        summ += cv;
        if (r == 0) mx = cv;
        if ((cid >> 2) == lane) {
            #pragma unroll
            for (int j = 0; j < 4; j++)
                if ((cid & 3) == j) v[j] = -INFINITY;
        }
    }
    mean5 = summ * 0.2f;
}

// ---------------------------------------------------------------------------
// Fully fused per-sentence kernel.
// Phases: (1) gather E fp32 + invI, (2) conv-norm via bf16 mma (W staged
// from global filters in 32-f slabs) -> invS, (3) exact fp32 numerator GEMM
// vs staged B2 chunks, (4) sims (alias dead E region), (5) top-5 + logit.
#define ESTRIDE 304               // padded E row stride (fp32)
#define SROWS 136                 // padded s rows
#define WF 32                     // filter-slab width
#define EB 308                    // W slab e-stride (bf16)
#define WSLAB (WF * 3 * EB)       // bf16 elems per slab = 29568 (59136 B)
#define ECHUNK 100                // B2 e-chunk rows (100*128*4 = 51200 B)

#define SZ_E      (SROWS * ESTRIDE * 4)           // 165376
#define OFF_W     SZ_E                            // W slab / B2 chunk region
#define SZ_W      (WSLAB * 2)                     // 59136
#define OFF_IDS   (SZ_E + SZ_W)                   // 224512
#define OFF_INVI  (OFF_IDS + 512)
#define OFF_INVS  (OFF_INVI + 512)
#define OFF_QSC   (OFF_INVS + 512)                // qinvI[32] qinvS[32] qm[32] slog[32]
#define DOC_SMEM  (OFF_QSC + 512)                 // 226560 total
// aliases inside the (dead) E region for phase 4:
#define OFF_SIMI  0
#define OFF_SIMS  (QLEN * SROWS * 4)              // 17408
#define OFF_PL2   (2 * QLEN * SROWS * 4)          // 34816
#define OFF_PL3   (3 * QLEN * SROWS * 4)          // 52224

__global__ void __launch_bounds__(256) k_doc(const float* __restrict__ embeds,
                                             const float* __restrict__ filters,
                                             const int* __restrict__ doc,
                                             const float* __restrict__ dsim,
                                             const int* __restrict__ question,
                                             const float* __restrict__ lin_w,
                                             const float* __restrict__ lin_b,
                                             float* __restrict__ out) {
    extern __shared__ unsigned char smem[];
    float* E      = (float*)smem;
    __nv_bfloat16* Ws = (__nv_bfloat16*)(smem + OFF_W);
    float* B2c    = (float*)(smem + OFF_W);
    int*   ids    = (int*)(smem + OFF_IDS);
    float* invI_s = (float*)(smem + OFF_INVI);
    float* invS_s = (float*)(smem + OFF_INVS);
    float* qinvI  = (float*)(smem + OFF_QSC);
    float* qinvS  = qinvI + QLEN;
    float* qmf    = qinvS + QLEN;
    float* slog   = qmf + QLEN;

    int n = blockIdx.x;
    int tid = threadIdx.x, lane = tid & 31, wid = tid >> 5;
    int q = tid & 31, ts = tid >> 5;
    int g = lane >> 2, c4 = lane & 3;

    // ---- phase 0: init ----
    for (int i = tid; i < SROWS * ESTRIDE; i += 256) E[i] = 0.f;
    if (tid < SLEN) ids[tid] = doc[(size_t)n * SLEN + tid];
    if (tid < QLEN) {
        qmf[tid] = (question[tid] > 1) ? 1.f : 0.f;
        qinvI[tid] = g_invq[tid];
        qinvS[tid] = g_invq[32 + tid];
    }
    __syncthreads();

    // ---- phase 1: gather E (fp32, exact) + invI ----
    for (int s = wid; s < SLEN; s += 8) {
        const float* row = embeds + (size_t)ids[s] * NE;
        float ss = 0.f;
        for (int e = lane; e < NE; e += 32) {
            float v = row[e];
            E[s * ESTRIDE + e] = v;
            ss += v * v;
        }
        #pragma unroll
        for (int o = 16; o > 0; o >>= 1) ss += __shfl_down_sync(0xffffffffu, ss, o);
        if (lane == 0) invI_s[s] = rsqrtf(ss);
    }
    __syncthreads();

    // ---- phase 2: conv-norm via bf16 mma ----
    int mbase = wid * 16;
    float rs0 = 0.f, rs1 = 0.f;
    for (int f8 = 0; f8 < 10; f8++) {
        for (int i = tid; i < WSLAB; i += 256) {
            int e = i % EB;
            int r = i / EB;
            int tap = r % 3, fl = r / 3;
            int f = f8 * WF + fl;
            float v = (f < NF && e < NE) ? filters[(size_t)f * 900 + tap * 300 + e] : 0.f;
            Ws[i] = __float2bfloat16(v);
        }
        __syncthreads();

        float cacc[4][4];
        #pragma unroll
        for (int nn = 0; nn < 4; nn++)
            #pragma unroll
            for (int j = 0; j < 4; j++) cacc[nn][j] = 0.f;

        #pragma unroll
        for (int tap = 0; tap < 3; tap++) {
            for (int ec = 0; ec < 19; ec++) {
                int e0 = ec * 16;
                int r = mbase + tap + g;
                float2 x0 = *(const float2*)&E[r * ESTRIDE + e0 + c4 * 2];
                float2 x1 = *(const float2*)&E[(r + 8) * ESTRIDE + e0 + c4 * 2];
                float2 x2 = *(const float2*)&E[r * ESTRIDE + e0 + 8 + c4 * 2];
                float2 x3 = *(const float2*)&E[(r + 8) * ESTRIDE + e0 + 8 + c4 * 2];
                __nv_bfloat162 h0 = __floats2bfloat162_rn(x0.x, x0.y);
                __nv_bfloat162 h1 = __floats2bfloat162_rn(x1.x, x1.y);
                __nv_bfloat162 h2 = __floats2bfloat162_rn(x2.x, x2.y);
                __nv_bfloat162 h3 = __floats2bfloat162_rn(x3.x, x3.y);
                uint32_t a0 = *(uint32_t*)&h0, a1 = *(uint32_t*)&h1;
                uint32_t a2 = *(uint32_t*)&h2, a3 = *(uint32_t*)&h3;
                #pragma unroll
                for (int nn = 0; nn < 4; nn++) {
                    int fl = nn * 8 + g;
                    uint32_t b0 = *(const uint32_t*)&Ws[(fl * 3 + tap) * EB + e0 + c4 * 2];
                    uint32_t b1 = *(const uint32_t*)&Ws[(fl * 3 + tap) * EB + e0 + 8 + c4 * 2];
                    asm volatile(
                        "mma.sync.aligned.m16n8k16.row.col.f32.bf16.bf16.f32 "
                        "{%0,%1,%2,%3}, {%4,%5,%6,%7}, {%8,%9}, {%0,%1,%2,%3};"
                        : "+f"(cacc[nn][0]), "+f"(cacc[nn][1]), "+f"(cacc[nn][2]), "+f"(cacc[nn][3])
                        : "r"(a0), "r"(a1), "r"(a2), "r"(a3), "r"(b0), "r"(b1));
                }
            }
        }
        #pragma unroll
        for (int nn = 0; nn < 4; nn++) {
            rs0 += cacc[nn][0] * cacc[nn][0] + cacc[nn][1] * cacc[nn][1];
            rs1 += cacc[nn][2] * cacc[nn][2] + cacc[nn][3] * cacc[nn][3];
        }
        __syncthreads();
    }
    rs0 += __shfl_xor_sync(0xffffffffu, rs0, 1);
    rs0 += __shfl_xor_sync(0xffffffffu, rs0, 2);
    rs1 += __shfl_xor_sync(0xffffffffu, rs1, 1);
    rs1 += __shfl_xor_sync(0xffffffffu, rs1, 2);
    if (c4 == 0) {
        invS_s[mbase + g] = rsqrtf(rs0);
        invS_s[mbase + g + 8] = rsqrtf(rs1);
    }
    __syncthreads();

    // ---- phase 3: exact fp32 numerator GEMM ----
    // acc[j][k] = sum_e E[ts+8k, e] * B2[e, q+32j]   (k<16: s = ts+8k < 128)
    float acc[4][16];
    #pragma unroll
    for (int j = 0; j < 4; j++)
        #pragma unroll
        for (int k = 0; k < 16; k++) acc[j][k] = 0.f;

    for (int e0 = 0; e0 < NE; e0 += ECHUNK) {
        for (int i = tid; i < ECHUNK * 128; i += 256)
            B2c[i] = g_B2[(e0 + (i >> 7)) * 128 + (i & 127)];
        __syncthreads();
        #pragma unroll 2
        for (int er = 0; er < ECHUNK; er += 2) {
            float b00 = B2c[er * 128 + q];
            float b01 = B2c[er * 128 + 128 + q];
            float b10 = B2c[er * 128 + 32 + q];
            float b11 = B2c[er * 128 + 160 + q];
            float b20 = B2c[er * 128 + 64 + q];
            float b21 = B2c[er * 128 + 192 + q];
            float b30 = B2c[er * 128 + 96 + q];
            float b31 = B2c[er * 128 + 224 + q];
            #pragma unroll
            for (int k = 0; k < 16; k++) {
                float2 ev = *(const float2*)&E[(ts + 8 * k) * ESTRIDE + e0 + er];
                acc[0][k] += ev.x * b00 + ev.y * b01;
                acc[1][k] += ev.x * b10 + ev.y * b11;
                acc[2][k] += ev.x * b20 + ev.y * b21;
                acc[3][k] += ev.x * b30 + ev.y * b31;
            }
        }
        __syncthreads();
    }

    // ---- phase 4: shifted planes + sims (alias dead E region) ----
    float* simI = (float*)(smem + OFF_SIMI);
    float* simS = (float*)(smem + OFF_SIMS);
    float* pl2  = (float*)(smem + OFF_PL2);
    float* pl3  = (float*)(smem + OFF_PL3);
    #pragma unroll
    for (int k = 0; k < 16; k++) {
        int s = ts + 8 * k;
        pl2[q * SROWS + s] = acc[2][k];
        pl3[q * SROWS + s] = acc[3][k];
    }
    // zero plane rows 128..135 (P of zero E rows is zero)
    {
        int s = SLEN + ts;
        pl2[q * SROWS + s] = 0.f;
        pl3[q * SROWS + s] = 0.f;
    }
    __syncthreads();

    float qi = qinvI[q], qs = qinvS[q], qm = qmf[q];
    #pragma unroll
    for (int k = 0; k < 16; k++) {
        int s = ts + 8 * k;
        float vI = acc[0][k] * qi * invI_s[s] * qm;
        if (ids[s] <= 1) vI = 0.f;
        float numS = acc[1][k] + pl2[q * SROWS + s + 1] + pl3[q * SROWS + s + 2];
        simI[q * SROWS + s] = vI;
        simS[q * SROWS + s] = numS * qs * invS_s[s];
    }
    __syncthreads();

    // ---- phase 5: top-5 features + logit + doc score ----
    float w0 = lin_w[0], w1 = lin_w[1], w2 = lin_w[2];
    float w3 = lin_w[3], w4 = lin_w[4], w5 = lin_w[5], b0 = lin_b[0];
    for (int qq = wid * 4; qq < wid * 4 + 4; qq++) {
        float mI, aI, mS, aS, mO, aO;
        top5(&simI[qq * SROWS], lane, mI, aI);
        top5(&simS[qq * SROWS], lane, mS, aS);
        top5(dsim + ((size_t)n * QLEN + qq) * SLEN, lane, mO, aO);
        float logit = b0 + w0 * mI + w1 * aI + w2 * mS + w3 * aS + w4 * mO + w5 * aO;
        if (lane == 0) slog[qq] = 1.f / (1.f + expf(-logit));
    }
    __syncthreads();

    if (wid == 0) {
        float v = slog[lane];
        #pragma unroll
        for (int o = 16; o > 0; o >>= 1) v += __shfl_down_sync(0xffffffffu, v, o);
        if (lane == 0) out[n] = v * (1.0f / QLEN);
    }
}

// ---------------------------------------------------------------------------
// Input order (setup_inputs): embeds, filters, lin_w, lin_b, question,
//                             doc1, doc2, doc1_sim, doc2_sim
extern "C" void kernel_launch(void* const* d_in, const int* in_sizes, int n_in,
                              void* d_out, int out_size) {
    const float* embeds   = (const float*)d_in[0];
    const float* filters  = (const float*)d_in[1];
    const float* lin_w    = (const float*)d_in[2];
    const float* lin_b    = (const float*)d_in[3];
    const int*   question = (const int*)d_in[4];
    const int*   doc1     = (const int*)d_in[5];
    const int*   doc2     = (const int*)d_in[6];
    const float* doc1_sim = (const float*)d_in[7];
    const float* doc2_sim = (const float*)d_in[8];
    float* out = (float*)d_out;

    cudaFuncSetAttribute(k_doc, cudaFuncAttributeMaxDynamicSharedMemorySize, DOC_SMEM);

    // question-side prep (tiny)
    k_prep_q<<<QLEN, 128>>>(embeds, question);
    k_qconv<<<dim3(QLEN, 3), 128>>>(filters);
    k_qnorm<<<QLEN, 128>>>();
    k_buildU<<<96, 128>>>(filters);

    // fully fused per-sentence pipeline
    k_doc<<<NSENT, 256, DOC_SMEM>>>(embeds, filters, doc1, doc1_sim, question, lin_w, lin_b, out);
    k_doc<<<NSENT, 256, DOC_SMEM>>>(embeds, filters, doc2, doc2_sim, question, lin_w, lin_b, out + NSENT);
}

// round 10
// speedup vs baseline: 1.0580x; 1.0580x over previous
#include <cuda_runtime.h>
#include <cuda_bf16.h>
#include <math.h>
#include <stdint.h>

// Problem constants
#define NV 50000
#define NE 300
#define NF 300
#define NFS 3
#define NSENT 1024
#define SLEN 128
#define QLEN 32

// Device-global scratch — ~231KB total (guard-safe; verified passing in R9).
__device__ float g_B2[NE * 128];     // [e][c]: c<32 = q_emb; 32+32k+q = U_k[q]
__device__ float g_qemb[QLEN * NE];
__device__ float g_qconv[QLEN * NF];
__device__ float g_invq[64];         // [0..31]=1/|q_emb|, [32..63]=1/|q_conv|

// ---------------------------------------------------------------------------
__device__ __forceinline__ uint32_t smem_u32(const void* p) {
    return (uint32_t)__cvta_generic_to_shared(p);
}

#define LDSM_X4(r0, r1, r2, r3, a) \
    asm volatile("ldmatrix.sync.aligned.m8n8.x4.shared.b16 {%0,%1,%2,%3}, [%4];" \
                 : "=r"(r0), "=r"(r1), "=r"(r2), "=r"(r3) : "r"(a))

#define LDSM_X4_T(r0, r1, r2, r3, a) \
    asm volatile("ldmatrix.sync.aligned.m8n8.x4.trans.shared.b16 {%0,%1,%2,%3}, [%4];" \
                 : "=r"(r0), "=r"(r1), "=r"(r2), "=r"(r3) : "r"(a))

#define MMA16816(d, a0, a1, a2, a3, b0, b1) \
    asm volatile("mma.sync.aligned.m16n8k16.row.col.f32.bf16.bf16.f32 " \
                 "{%0,%1,%2,%3}, {%4,%5,%6,%7}, {%8,%9}, {%0,%1,%2,%3};" \
                 : "+f"((d)[0]), "+f"((d)[1]), "+f"((d)[2]), "+f"((d)[3]) \
                 : "r"(a0), "r"(a1), "r"(a2), "r"(a3), "r"(b0), "r"(b1))

// ---------------------------------------------------------------------------
// K1a: gather q_emb, fill B2 cols 0..31, compute 1/|q_emb|
__global__ void k_prep_q(const float* __restrict__ embeds, const int* __restrict__ question) {
    int q = blockIdx.x;
    int tid = threadIdx.x;
    int tok = question[q];
    const float* src = embeds + (size_t)tok * NE;
    float ss = 0.f;
    for (int e = tid; e < NE; e += 128) {
        float v = src[e];
        g_qemb[q * NE + e] = v;
        g_B2[e * 128 + q] = v;
        ss += v * v;
    }
    __shared__ float red[128];
    red[tid] = ss;
    __syncthreads();
    for (int o = 64; o > 0; o >>= 1) {
        if (tid < o) red[tid] += red[tid + o];
        __syncthreads();
    }
    if (tid == 0) g_invq[q] = 1.0f / sqrtf(red[0]);
}

// K1b: q_conv[q,f] = sum_k sum_e q_emb[q+k,e] * W[f,k,e]
__global__ void k_qconv(const float* __restrict__ filters) {
    int q = blockIdx.x;
    int f = blockIdx.y * 128 + threadIdx.x;
    if (f >= NF) return;
    float acc = 0.f;
    for (int k = 0; k < NFS; k++) {
        if (q + k >= QLEN) break;
        const float* w = filters + (size_t)f * 900 + k * 300;
        const float* x = g_qemb + (q + k) * NE;
        #pragma unroll 4
        for (int e = 0; e < NE; e++) acc += x[e] * w[e];
    }
    g_qconv[q * NF + f] = acc;
}

// K1c: 1/|q_conv[q]|
__global__ void k_qnorm(void) {
    int q = blockIdx.x;
    int tid = threadIdx.x;
    float ss = 0.f;
    for (int f = tid; f < NF; f += 128) {
        float v = g_qconv[q * NF + f];
        ss += v * v;
    }
    __shared__ float red[128];
    red[tid] = ss;
    __syncthreads();
    for (int o = 64; o > 0; o >>= 1) {
        if (tid < o) red[tid] += red[tid + o];
        __syncthreads();
    }
    if (tid == 0) g_invq[32 + q] = 1.0f / sqrtf(red[0]);
}

// K1d: U[k,q,e] -> B2 col 32+32k+q. Grid (96, 3): e-split for occupancy,
// 4 accumulators to break the FMA chain / raise MLP.
__global__ void k_buildU(const float* __restrict__ filters) {
    int c = blockIdx.x;
    int k = c >> 5, q = c & 31;
    int e = blockIdx.y * 100 + threadIdx.x;
    if (threadIdx.x >= 100) return;
    const float* qc = g_qconv + q * NF;
    const float* fb = filters + k * 300 + e;
    float a0 = 0.f, a1 = 0.f, a2 = 0.f, a3 = 0.f;
    for (int f = 0; f < NF; f += 4) {
        a0 += fb[(size_t)(f + 0) * 900] * qc[f + 0];
        a1 += fb[(size_t)(f + 1) * 900] * qc[f + 1];
        a2 += fb[(size_t)(f + 2) * 900] * qc[f + 2];
        a3 += fb[(size_t)(f + 3) * 900] * qc[f + 3];
    }
    g_B2[e * 128 + 32 + c] = (a0 + a1) + (a2 + a3);
}

// ---------------------------------------------------------------------------
// Warp-cooperative top-5 over 128 values: returns max and mean-of-top-5.
__device__ __forceinline__ void top5(const float* __restrict__ row, int lane,
                                     float& mx, float& mean5) {
    float v[4];
    #pragma unroll
    for (int j = 0; j < 4; j++) v[j] = row[lane + 32 * j];
    float summ = 0.f;
    mx = 0.f;
    #pragma unroll
    for (int r = 0; r < 5; r++) {
        float bv = v[0];
        int bj = 0;
        #pragma unroll
        for (int j = 1; j < 4; j++)
            if (v[j] > bv) { bv = v[j]; bj = j; }
        float cv = bv;
        int cid = (lane << 2) | bj;
        #pragma unroll
        for (int o = 16; o > 0; o >>= 1) {
            float ov = __shfl_down_sync(0xffffffffu, cv, o);
            int oi = __shfl_down_sync(0xffffffffu, cid, o);
            if (ov > cv || (ov == cv && oi < cid)) { cv = ov; cid = oi; }
        }
        cv = __shfl_sync(0xffffffffu, cv, 0);
        cid = __shfl_sync(0xffffffffu, cid, 0);
        summ += cv;
        if (r == 0) mx = cv;
        if ((cid >> 2) == lane) {
            #pragma unroll
            for (int j = 0; j < 4; j++)
                if ((cid & 3) == j) v[j] = -INFINITY;
        }
    }
    mean5 = summ * 0.2f;
}

// ---------------------------------------------------------------------------
// Fully fused per-sentence kernel, tensor-core version.
// Phase 1: gather E as bf16 hi+lo planes (fp32 norms -> invI).
// Phase 2: conv row-norms via ldmatrix + mma (W slabs staged bf16) -> invS.
// Phase 3: numerators P = E @ B2 via 3-pass bf16 hi/lo mma (~fp32 precision).
// Phase 4: sims from P plane. Phase 5: top-5 + logit + doc score.
#define EROW 312                 // bf16 row stride: 624B = 39*16B, banks conflict-free
#define ERN  132                 // 128 rows + 2 lookahead + pad
#define SR   136                 // fp32 plane s-stride

#define OFF_EHI  0
#define SZ_EP    (ERN * EROW * 2)          // 82368
#define OFF_ELO  SZ_EP
#define OFF_WS   (2 * SZ_EP)               // 164736
#define SZ_WS    (32 * 3 * EROW * 2)       // 59904
#define OFF_IDS  (OFF_WS + SZ_WS)          // 224640
#define OFF_INVI (OFF_IDS + 512)
#define OFF_INVS (OFF_INVI + 512)
#define OFF_QSC  (OFF_INVS + 512)
#define DOC_SMEM (OFF_QSC + 512)           // 226688 B
// phase-3 B2 chunk aliases WS region (hi, lo):
#define OFF_B2H  OFF_WS
#define OFF_B2L  (OFF_WS + 80 * 136 * 2)   // +21760
// late-phase aliases inside dead E region:
#define OFF_P    0                         // 128*SR*4 = 69632
#define OFF_SIMI 69632
#define OFF_SIMS 87040

__global__ void __launch_bounds__(256) k_doc(const float* __restrict__ embeds,
                                             const float* __restrict__ filters,
                                             const int* __restrict__ doc,
                                             const float* __restrict__ dsim,
                                             const int* __restrict__ question,
                                             const float* __restrict__ lin_w,
                                             const float* __restrict__ lin_b,
                                             float* __restrict__ out) {
    extern __shared__ unsigned char smem[];
    __nv_bfloat16* EH = (__nv_bfloat16*)(smem + OFF_EHI);
    __nv_bfloat16* ELo = (__nv_bfloat16*)(smem + OFF_ELO);
    __nv_bfloat16* WS = (__nv_bfloat16*)(smem + OFF_WS);
    __nv_bfloat16* B2H = (__nv_bfloat16*)(smem + OFF_B2H);
    __nv_bfloat16* B2L = (__nv_bfloat16*)(smem + OFF_B2L);
    int*   ids    = (int*)(smem + OFF_IDS);
    float* invI_s = (float*)(smem + OFF_INVI);
    float* invS_s = (float*)(smem + OFF_INVS);
    float* qinvI  = (float*)(smem + OFF_QSC);
    float* qinvS  = qinvI + QLEN;
    float* qmf    = qinvS + QLEN;
    float* slog   = qmf + QLEN;

    int n = blockIdx.x;
    int tid = threadIdx.x, lane = tid & 31, wid = tid >> 5;
    int g2 = lane >> 2, c4 = lane & 3;          // mma fragment coords
    int t8 = lane >> 3, rr = lane & 7;          // ldmatrix lane coords
    int arow = (t8 & 1) * 8 + rr;               // A / trans-B row offset
    int acol = (t8 >> 1) * 8;                   // A / trans-B col offset
    int brow = (t8 >> 1) * 8 + rr;              // non-trans B row offset
    int bcol = (t8 & 1) * 8;                    // non-trans B col offset
    int mbase = wid * 16;

    // ---- phase 0: zero E planes, load ids + q-side constants ----
    {
        uint32_t* z = (uint32_t*)smem;
        for (int i = tid; i < 2 * SZ_EP / 4; i += 256) z[i] = 0u;
    }
    if (tid < SLEN) ids[tid] = doc[(size_t)n * SLEN + tid];
    if (tid < QLEN) {
        qmf[tid] = (question[tid] > 1) ? 1.f : 0.f;
        qinvI[tid] = g_invq[tid];
        qinvS[tid] = g_invq[32 + tid];
    }
    __syncthreads();

    // ---- phase 1: gather E -> bf16 hi/lo planes + fp32 invI ----
    for (int s = wid; s < SLEN; s += 8) {
        const float* row = embeds + (size_t)ids[s] * NE;
        float ss = 0.f;
        for (int e = lane; e < NE; e += 32) {
            float v = row[e];
            __nv_bfloat16 bh = __float2bfloat16(v);
            EH[s * EROW + e] = bh;
            ELo[s * EROW + e] = __float2bfloat16(v - __bfloat162float(bh));
            ss += v * v;
        }
        #pragma unroll
        for (int o = 16; o > 0; o >>= 1) ss += __shfl_down_sync(0xffffffffu, ss, o);
        if (lane == 0) invI_s[s] = rsqrtf(ss);
    }
    __syncthreads();

    // ---- phase 2: conv row-norms via ldmatrix + mma ----
    uint32_t eh_u = smem_u32(EH);
    uint32_t ws_u = smem_u32(WS);
    float rs0 = 0.f, rs1 = 0.f;
    for (int f8 = 0; f8 < 10; f8++) {
        for (int i = tid; i < 32 * 3 * EROW; i += 256) {
            int e = i % EROW;
            int r = i / EROW;
            int tap = r % 3, fl = r / 3;
            int f = f8 * 32 + fl;
            float v = (f < NF && e < NE) ? filters[(size_t)f * 900 + tap * 300 + e] : 0.f;
            WS[i] = __float2bfloat16(v);
        }
        __syncthreads();

        float cc[4][4];
        #pragma unroll
        for (int j = 0; j < 4; j++)
            #pragma unroll
            for (int x = 0; x < 4; x++) cc[j][x] = 0.f;

        #pragma unroll
        for (int tap = 0; tap < 3; tap++) {
            for (int ec = 0; ec < 19; ec++) {
                uint32_t a0, a1, a2, a3;
                uint32_t aaddr = eh_u + (uint32_t)(((mbase + tap + arow) * EROW + ec * 16 + acol) * 2);
                LDSM_X4(a0, a1, a2, a3, aaddr);
                #pragma unroll
                for (int np = 0; np < 2; np++) {
                    uint32_t b0, b1, b2, b3;
                    uint32_t baddr = ws_u + (uint32_t)((((np * 16 + brow) * 3 + tap) * EROW + ec * 16 + bcol) * 2);
                    LDSM_X4(b0, b1, b2, b3, baddr);
                    MMA16816(cc[np * 2], a0, a1, a2, a3, b0, b1);
                    MMA16816(cc[np * 2 + 1], a0, a1, a2, a3, b2, b3);
                }
            }
        }
        #pragma unroll
        for (int j = 0; j < 4; j++) {
            rs0 += cc[j][0] * cc[j][0] + cc[j][1] * cc[j][1];
            rs1 += cc[j][2] * cc[j][2] + cc[j][3] * cc[j][3];
        }
        __syncthreads();
    }
    rs0 += __shfl_xor_sync(0xffffffffu, rs0, 1);
    rs0 += __shfl_xor_sync(0xffffffffu, rs0, 2);
    rs1 += __shfl_xor_sync(0xffffffffu, rs1, 1);
    rs1 += __shfl_xor_sync(0xffffffffu, rs1, 2);
    if (c4 == 0) {
        invS_s[mbase + g2] = rsqrtf(rs0);
        invS_s[mbase + g2 + 8] = rsqrtf(rs1);
    }
    __syncthreads();

    // ---- phase 3: P = E @ B2 via 3-pass bf16 hi/lo mma ----
    uint32_t el_u = smem_u32(ELo);
    uint32_t bh_u = smem_u32(B2H);
    uint32_t bl_u = smem_u32(B2L);
    float pa[16][4];
    #pragma unroll
    for (int j = 0; j < 16; j++)
        #pragma unroll
        for (int x = 0; x < 4; x++) pa[j][x] = 0.f;

    for (int ch = 0; ch < 4; ch++) {
        int ebase = ch * 80;
        int ecnt = (ch == 3) ? 64 : 80;
        for (int i = tid; i < ecnt * 136; i += 256) {
            int e = ebase + i / 136;
            int c = i % 136;
            float v = (e < NE && c < 128) ? g_B2[e * 128 + c] : 0.f;
            __nv_bfloat16 vh = __float2bfloat16(v);
            B2H[i] = vh;
            B2L[i] = __float2bfloat16(v - __bfloat162float(vh));
        }
        __syncthreads();

        int nk = ecnt >> 4;
        for (int kt = 0; kt < nk; kt++) {
            int eg = ebase + kt * 16;
            uint32_t ah0, ah1, ah2, ah3, al0, al1, al2, al3;
            uint32_t ahaddr = eh_u + (uint32_t)(((mbase + arow) * EROW + eg + acol) * 2);
            uint32_t aladdr = el_u + (uint32_t)(((mbase + arow) * EROW + eg + acol) * 2);
            LDSM_X4(ah0, ah1, ah2, ah3, ahaddr);
            LDSM_X4(al0, al1, al2, al3, aladdr);
            #pragma unroll
            for (int np = 0; np < 8; np++) {
                uint32_t h0, h1, h2, h3, l0, l1, l2, l3;
                uint32_t off = (uint32_t)(((kt * 16 + arow) * 136 + np * 16 + acol) * 2);
                LDSM_X4_T(h0, h1, h2, h3, bh_u + off);
                LDSM_X4_T(l0, l1, l2, l3, bl_u + off);
                MMA16816(pa[np * 2], ah0, ah1, ah2, ah3, h0, h1);
                MMA16816(pa[np * 2], ah0, ah1, ah2, ah3, l0, l1);
                MMA16816(pa[np * 2], al0, al1, al2, al3, h0, h1);
                MMA16816(pa[np * 2 + 1], ah0, ah1, ah2, ah3, h2, h3);
                MMA16816(pa[np * 2 + 1], ah0, ah1, ah2, ah3, l2, l3);
                MMA16816(pa[np * 2 + 1], al0, al1, al2, al3, h2, h3);
            }
        }
        __syncthreads();
    }

    // store P plane [c][s] (E region dead)
    float* P = (float*)(smem + OFF_P);
    #pragma unroll
    for (int nt = 0; nt < 16; nt++) {
        int c = nt * 8 + c4 * 2;
        int s = mbase + g2;
        P[c * SR + s] = pa[nt][0];
        P[(c + 1) * SR + s] = pa[nt][1];
        P[c * SR + s + 8] = pa[nt][2];
        P[(c + 1) * SR + s + 8] = pa[nt][3];
    }
    for (int i = tid; i < 128 * 8; i += 256) {
        int c = i >> 3, s = SLEN + (i & 7);
        P[c * SR + s] = 0.f;
    }
    __syncthreads();

    // ---- phase 4: sims ----
    float* simI = (float*)(smem + OFF_SIMI);
    float* simS = (float*)(smem + OFF_SIMS);
    {
        int q = lane, ts = wid;
        float qi = qinvI[q], qs = qinvS[q], qm = qmf[q];
        #pragma unroll
        for (int k = 0; k < 16; k++) {
            int s = ts + 8 * k;
            float vI = P[q * SR + s] * qi * invI_s[s] * qm;
            if (ids[s] <= 1) vI = 0.f;
            float num = P[(32 + q) * SR + s] + P[(64 + q) * SR + s + 1] + P[(96 + q) * SR + s + 2];
            simI[q * SR + s] = vI;
            simS[q * SR + s] = num * qs * invS_s[s];
        }
    }
    __syncthreads();

    // ---- phase 5: top-5 features + logit + doc score ----
    float w0 = lin_w[0], w1 = lin_w[1], w2 = lin_w[2];
    float w3 = lin_w[3], w4 = lin_w[4], w5 = lin_w[5], b0 = lin_b[0];
    for (int qq = wid * 4; qq < wid * 4 + 4; qq++) {
        float mI, aI, mS, aS, mO, aO;
        top5(&simI[qq * SR], lane, mI, aI);
        top5(&simS[qq * SR], lane, mS, aS);
        top5(dsim + ((size_t)n * QLEN + qq) * SLEN, lane, mO, aO);
        float logit = b0 + w0 * mI + w1 * aI + w2 * mS + w3 * aS + w4 * mO + w5 * aO;
        if (lane == 0) slog[qq] = 1.f / (1.f + expf(-logit));
    }
    __syncthreads();

    if (wid == 0) {
        float v = slog[lane];
        #pragma unroll
        for (int o = 16; o > 0; o >>= 1) v += __shfl_down_sync(0xffffffffu, v, o);
        if (lane == 0) out[n] = v * (1.0f / QLEN);
    }
}

// ---------------------------------------------------------------------------
// Input order: embeds, filters, lin_w, lin_b, question, doc1, doc2,
//              doc1_sim, doc2_sim
extern "C" void kernel_launch(void* const* d_in, const int* in_sizes, int n_in,
                              void* d_out, int out_size) {
    const float* embeds   = (const float*)d_in[0];
    const float* filters  = (const float*)d_in[1];
    const float* lin_w    = (const float*)d_in[2];
    const float* lin_b    = (const float*)d_in[3];
    const int*   question = (const int*)d_in[4];
    const int*   doc1     = (const int*)d_in[5];
    const int*   doc2     = (const int*)d_in[6];
    const float* doc1_sim = (const float*)d_in[7];
    const float* doc2_sim = (const float*)d_in[8];
    float* out = (float*)d_out;

    cudaFuncSetAttribute(k_doc, cudaFuncAttributeMaxDynamicSharedMemorySize, DOC_SMEM);

    k_prep_q<<<QLEN, 128>>>(embeds, question);
    k_qconv<<<dim3(QLEN, 3), 128>>>(filters);
    k_qnorm<<<QLEN, 128>>>();
    k_buildU<<<dim3(96, 3), 128>>>(filters);

    k_doc<<<NSENT, 256, DOC_SMEM>>>(embeds, filters, doc1, doc1_sim, question, lin_w, lin_b, out);
    k_doc<<<NSENT, 256, DOC_SMEM>>>(embeds, filters, doc2, doc2_sim, question, lin_w, lin_b, out + NSENT);
}

// round 12
// speedup vs baseline: 2.4147x; 2.2822x over previous
#include <cuda_runtime.h>
#include <cuda_bf16.h>
#include <math.h>
#include <stdint.h>

#define NV 50000
#define NE 300
#define NF 300
#define NSENT 1024
#define SLEN 128
#define QLEN 32

// Device-global scratch — ~231KB (guard-safe, verified passing R9/R10).
__device__ float g_B2[NE * 128];     // [e][c]: c<32 = q_emb; 32+32k+q = U_k[q]
__device__ float g_qemb[QLEN * NE];
__device__ float g_qconv[QLEN * NF];
__device__ float g_invq[64];         // [0..31]=1/|q_emb|, [32..63]=1/|q_conv|

// ---------------------------------------------------------------------------
__device__ __forceinline__ uint32_t smem_u32(const void* p) {
    return (uint32_t)__cvta_generic_to_shared(p);
}

#define LDSM_X4(r0, r1, r2, r3, a) \
    asm volatile("ldmatrix.sync.aligned.m8n8.x4.shared.b16 {%0,%1,%2,%3}, [%4];" \
                 : "=r"(r0), "=r"(r1), "=r"(r2), "=r"(r3) : "r"(a))

#define MMA16816(d, a0, a1, a2, a3, b0, b1) \
    asm volatile("mma.sync.aligned.m16n8k16.row.col.f32.bf16.bf16.f32 " \
                 "{%0,%1,%2,%3}, {%4,%5,%6,%7}, {%8,%9}, {%0,%1,%2,%3};" \
                 : "+f"((d)[0]), "+f"((d)[1]), "+f"((d)[2]), "+f"((d)[3]) \
                 : "r"(a0), "r"(a1), "r"(a2), "r"(a3), "r"(b0), "r"(b1))

// ---------------------------------------------------------------------------
// Prep kernels (R10-proven)
__global__ void k_prep_q(const float* __restrict__ embeds, const int* __restrict__ question) {
    int q = blockIdx.x;
    int tid = threadIdx.x;
    int tok = question[q];
    const float* src = embeds + (size_t)tok * NE;
    float ss = 0.f;
    for (int e = tid; e < NE; e += 128) {
        float v = src[e];
        g_qemb[q * NE + e] = v;
        g_B2[e * 128 + q] = v;
        ss += v * v;
    }
    __shared__ float red[128];
    red[tid] = ss;
    __syncthreads();
    for (int o = 64; o > 0; o >>= 1) {
        if (tid < o) red[tid] += red[tid + o];
        __syncthreads();
    }
    if (tid == 0) g_invq[q] = rsqrtf(red[0]);
}

__global__ void k_qconv(const float* __restrict__ filters) {
    int q = blockIdx.x;
    int f = blockIdx.y * 128 + threadIdx.x;
    if (f >= NF) return;
    float acc = 0.f;
    for (int k = 0; k < 3; k++) {
        if (q + k >= QLEN) break;
        const float* w = filters + (size_t)f * 900 + k * 300;
        const float* x = g_qemb + (q + k) * NE;
        #pragma unroll 4
        for (int e = 0; e < NE; e++) acc += x[e] * w[e];
    }
    g_qconv[q * NF + f] = acc;
}

// buildU + folded qnorm
__global__ void k_buildU(const float* __restrict__ filters) {
    __shared__ float red[128];
    int c = blockIdx.x;
    int k = c >> 5, q = c & 31;
    int e = blockIdx.y * 100 + threadIdx.x;
    if (threadIdx.x < 100) {
        const float* qc = g_qconv + q * NF;
        const float* fb = filters + k * 300 + e;
        float a0 = 0.f, a1 = 0.f, a2 = 0.f, a3 = 0.f;
        for (int f = 0; f < NF; f += 4) {
            a0 += fb[(size_t)(f + 0) * 900] * qc[f + 0];
            a1 += fb[(size_t)(f + 1) * 900] * qc[f + 1];
            a2 += fb[(size_t)(f + 2) * 900] * qc[f + 2];
            a3 += fb[(size_t)(f + 3) * 900] * qc[f + 3];
        }
        g_B2[e * 128 + 32 + c] = (a0 + a1) + (a2 + a3);
    }
    if (blockIdx.y == 0 && blockIdx.x < 32) {
        int qq = blockIdx.x;
        int tid = threadIdx.x;
        float ss = 0.f;
        for (int f = tid; f < NF; f += 128) {
            float v = g_qconv[qq * NF + f];
            ss += v * v;
        }
        red[tid] = ss;
        __syncthreads();
        for (int o = 64; o > 0; o >>= 1) {
            if (tid < o) red[tid] += red[tid + o];
            __syncthreads();
        }
        if (tid == 0) g_invq[32 + qq] = rsqrtf(red[0]);
    }
}

// ---------------------------------------------------------------------------
// top-5 over 4 register values per lane (128 values per warp) — R10-proven logic
__device__ __forceinline__ void top5v(float v0, float v1, float v2, float v3,
                                      int lane, float& mx, float& mean5) {
    float v[4] = {v0, v1, v2, v3};
    float summ = 0.f;
    mx = 0.f;
    #pragma unroll
    for (int r = 0; r < 5; r++) {
        float bv = v[0];
        int bj = 0;
        #pragma unroll
        for (int j = 1; j < 4; j++)
            if (v[j] > bv) { bv = v[j]; bj = j; }
        float cv = bv;
        int cid = (lane << 2) | bj;
        #pragma unroll
        for (int o = 16; o > 0; o >>= 1) {
            float ov = __shfl_down_sync(0xffffffffu, cv, o);
            int oi = __shfl_down_sync(0xffffffffu, cid, o);
            if (ov > cv || (ov == cv && oi < cid)) { cv = ov; cid = oi; }
        }
        cv = __shfl_sync(0xffffffffu, cv, 0);
        cid = __shfl_sync(0xffffffffu, cid, 0);
        summ += cv;
        if (r == 0) mx = cv;
        if ((cid >> 2) == lane) {
            #pragma unroll
            for (int j = 0; j < 4; j++)
                if ((cid & 3) == j) v[j] = -INFINITY;
        }
    }
    mean5 = summ * 0.2f;
}

// ---------------------------------------------------------------------------
// Fused per-sentence kernel (mma.sync), 103KB smem -> 2 CTAs/SM.
// Phase 1: gather E bf16 (single plane) + invI.
// Phase 2: conv norms: per f-slab(32): accumulate 3 taps via shifted-A mma.
// Phase 3: P = E @ B2, single-pass bf16, B2 staged pre-transposed [c][e].
// Phase 4/5: sims on the fly -> top-5 -> logit -> score.
#define EROW 312                  // bf16 row stride (624B: conflict-free, R10-proven)
#define ERN  130                  // 128 rows + 2 zero lookahead
#define OFF_E    0
#define SZ_E     (ERN * EROW * 2)          // 81120
#define OFF_W    SZ_E                      // 19968-byte staging slab (W / B2)
#define SZ_W     (32 * EROW * 2)
#define OFF_IDS  (OFF_W + SZ_W)            // 101088
#define OFF_INVI (OFF_IDS + 512)
#define OFF_INVS (OFF_INVI + 512)
#define OFF_QV   (OFF_INVS + 512)          // qinvI[32] qinvS[32] qmf[32] slog[32]
#define DOC_SMEM (OFF_QV + 512)            // 103136
#define PSTRIDE  132                       // P[c][s] fp32, aliases dead E region

__global__ void __launch_bounds__(256, 2) k_doc(const float* __restrict__ embeds,
                                                const float* __restrict__ filters,
                                                const int* __restrict__ doc1,
                                                const int* __restrict__ doc2,
                                                const float* __restrict__ dsim1,
                                                const float* __restrict__ dsim2,
                                                const int* __restrict__ question,
                                                const float* __restrict__ lin_w,
                                                const float* __restrict__ lin_b,
                                                float* __restrict__ out) {
    extern __shared__ unsigned char smem[];
    __nv_bfloat16* Eb = (__nv_bfloat16*)(smem + OFF_E);
    __nv_bfloat16* Ws = (__nv_bfloat16*)(smem + OFF_W);
    int*   ids    = (int*)(smem + OFF_IDS);
    float* invI_s = (float*)(smem + OFF_INVI);
    float* invS_s = (float*)(smem + OFF_INVS);
    float* qinvI  = (float*)(smem + OFF_QV);
    float* qinvS  = qinvI + 32;
    float* qmf    = qinvS + 32;
    float* slog   = qmf + 32;
    float* P      = (float*)(smem + OFF_E);   // alias: E dead before P written

    int bn = blockIdx.x;
    const int* doc = (bn < NSENT) ? doc1 : doc2;
    const float* dsim = (bn < NSENT) ? dsim1 : dsim2;
    int n = (bn < NSENT) ? bn : bn - NSENT;

    int tid = threadIdx.x, lane = tid & 31, wid = tid >> 5;
    int g2 = lane >> 2, c4 = lane & 3;
    int t8 = lane >> 3, rr = lane & 7;
    int arow = (t8 & 1) * 8 + rr;
    int acol = (t8 >> 1) * 8;
    int brow = (t8 >> 1) * 8 + rr;
    int bcol = (t8 & 1) * 8;
    int mbase = wid * 16;

    // ---- phase 0: zero E plane, ids + q-side constants ----
    {
        uint32_t* z = (uint32_t*)(smem + OFF_E);
        for (int i = tid; i < SZ_E / 4; i += 256) z[i] = 0u;
    }
    if (tid < SLEN) ids[tid] = doc[(size_t)n * SLEN + tid];
    if (tid < QLEN) {
        qmf[tid] = (question[tid] > 1) ? 1.f : 0.f;
        qinvI[tid] = g_invq[tid];
        qinvS[tid] = g_invq[32 + tid];
    }
    __syncthreads();

    // ---- phase 1: gather E -> bf16 + invI ----
    for (int s = wid; s < SLEN; s += 8) {
        const float* row = embeds + (size_t)ids[s] * NE;
        float ss = 0.f;
        for (int e = lane; e < NE; e += 32) {
            float v = row[e];
            Eb[s * EROW + e] = __float2bfloat16(v);
            ss += v * v;
        }
        #pragma unroll
        for (int o = 16; o > 0; o >>= 1) ss += __shfl_down_sync(0xffffffffu, ss, o);
        if (lane == 0) invI_s[s] = rsqrtf(ss);
    }

    uint32_t eh_u = smem_u32(Eb);
    uint32_t ws_u = smem_u32(Ws);

    // ---- phase 2: conv norms. 10 f-slabs; 3 taps accumulated per slab ----
    float rs0 = 0.f, rs1 = 0.f;
    for (int slab = 0; slab < 10; slab++) {
        float cc[4][4];
        #pragma unroll
        for (int j = 0; j < 4; j++)
            #pragma unroll
            for (int x = 0; x < 4; x++) cc[j][x] = 0.f;

        for (int tap = 0; tap < 3; tap++) {
            __syncthreads();
            // stage W(slab, tap): [32 f x 304 e] bf16, row stride EROW
            for (int i = tid; i < 32 * 304; i += 256) {
                int fl = i / 304, e = i - fl * 304;
                int f = slab * 32 + fl;
                float v = (f < NF && e < NE) ? filters[(size_t)f * 900 + tap * 300 + e] : 0.f;
                Ws[fl * EROW + e] = __float2bfloat16(v);
            }
            __syncthreads();
            for (int ec = 0; ec < 19; ec++) {
                uint32_t a0, a1, a2, a3;
                uint32_t aaddr = eh_u + (uint32_t)(((mbase + tap + arow) * EROW + ec * 16 + acol) * 2);
                LDSM_X4(a0, a1, a2, a3, aaddr);
                #pragma unroll
                for (int np = 0; np < 2; np++) {
                    uint32_t b0, b1, b2, b3;
                    uint32_t baddr = ws_u + (uint32_t)(((np * 16 + brow) * EROW + ec * 16 + bcol) * 2);
                    LDSM_X4(b0, b1, b2, b3, baddr);
                    MMA16816(cc[np * 2], a0, a1, a2, a3, b0, b1);
                    MMA16816(cc[np * 2 + 1], a0, a1, a2, a3, b2, b3);
                }
            }
        }
        #pragma unroll
        for (int j = 0; j < 4; j++) {
            rs0 += cc[j][0] * cc[j][0] + cc[j][1] * cc[j][1];
            rs1 += cc[j][2] * cc[j][2] + cc[j][3] * cc[j][3];
        }
    }
    rs0 += __shfl_xor_sync(0xffffffffu, rs0, 1);
    rs0 += __shfl_xor_sync(0xffffffffu, rs0, 2);
    rs1 += __shfl_xor_sync(0xffffffffu, rs1, 1);
    rs1 += __shfl_xor_sync(0xffffffffu, rs1, 2);
    if (c4 == 0) {
        invS_s[mbase + g2] = rsqrtf(rs0);
        invS_s[mbase + g2 + 8] = rsqrtf(rs1);
    }

    // ---- phase 3: P = E @ B2, single-pass bf16, 4 c-slabs of 32 ----
    float pa[4][4][4];
    #pragma unroll
    for (int cs = 0; cs < 4; cs++)
        #pragma unroll
        for (int nt = 0; nt < 4; nt++)
            #pragma unroll
            for (int x = 0; x < 4; x++) pa[cs][nt][x] = 0.f;

    for (int cs = 0; cs < 4; cs++) {
        __syncthreads();
        // stage B2 slab pre-transposed: Ws[cl][e] = B2[e][cs*32+cl]
        for (int i = tid; i < 304 * 32; i += 256) {
            int e = i >> 5, cl = i & 31;
            float v = (e < NE) ? g_B2[e * 128 + cs * 32 + cl] : 0.f;
            Ws[cl * EROW + e] = __float2bfloat16(v);
        }
        __syncthreads();
        for (int ec = 0; ec < 19; ec++) {
            uint32_t a0, a1, a2, a3;
            uint32_t aaddr = eh_u + (uint32_t)(((mbase + arow) * EROW + ec * 16 + acol) * 2);
            LDSM_X4(a0, a1, a2, a3, aaddr);
            #pragma unroll
            for (int np = 0; np < 2; np++) {
                uint32_t b0, b1, b2, b3;
                uint32_t baddr = ws_u + (uint32_t)(((np * 16 + brow) * EROW + ec * 16 + bcol) * 2);
                LDSM_X4(b0, b1, b2, b3, baddr);
                MMA16816(pa[cs][np * 2], a0, a1, a2, a3, b0, b1);
                MMA16816(pa[cs][np * 2 + 1], a0, a1, a2, a3, b2, b3);
            }
        }
    }
    __syncthreads();   // all E reads done; safe to overwrite with P

    // store P[c][s] from fragments (c fragment cols = nt*8 + c4*2, rows g2/g2+8)
    #pragma unroll
    for (int cs = 0; cs < 4; cs++)
        #pragma unroll
        for (int nt = 0; nt < 4; nt++) {
            int c = cs * 32 + nt * 8 + c4 * 2;
            int s = mbase + g2;
            P[c * PSTRIDE + s] = pa[cs][nt][0];
            P[(c + 1) * PSTRIDE + s] = pa[cs][nt][1];
            P[c * PSTRIDE + s + 8] = pa[cs][nt][2];
            P[(c + 1) * PSTRIDE + s + 8] = pa[cs][nt][3];
        }
    __syncthreads();

    // ---- phase 4/5: sims on the fly -> top-5 -> logit -> score ----
    float w0 = lin_w[0], w1 = lin_w[1], w2 = lin_w[2];
    float w3 = lin_w[3], w4 = lin_w[4], w5 = lin_w[5], b0 = lin_b[0];
    for (int qq = wid * 4; qq < wid * 4 + 4; qq++) {
        float qi = qinvI[qq], qs = qinvS[qq], qm = qmf[qq];
        float vI[4], vS[4], vO[4];
        #pragma unroll
        for (int j = 0; j < 4; j++) {
            int s = lane + 32 * j;
            float a = P[qq * PSTRIDE + s] * qi * invI_s[s] * qm;
            if (ids[s] <= 1) a = 0.f;
            vI[j] = a;
            float num = P[(32 + qq) * PSTRIDE + s];
            if (s + 1 < SLEN) num += P[(64 + qq) * PSTRIDE + s + 1];
            if (s + 2 < SLEN) num += P[(96 + qq) * PSTRIDE + s + 2];
            vS[j] = num * qs * invS_s[s];
            vO[j] = dsim[((size_t)n * QLEN + qq) * SLEN + s];
        }
        float mI, aI, mS, aS, mO, aO;
        top5v(vI[0], vI[1], vI[2], vI[3], lane, mI, aI);
        top5v(vS[0], vS[1], vS[2], vS[3], lane, mS, aS);
        top5v(vO[0], vO[1], vO[2], vO[3], lane, mO, aO);
        float logit = b0 + w0 * mI + w1 * aI + w2 * mS + w3 * aS + w4 * mO + w5 * aO;
        if (lane == 0) slog[qq] = 1.f / (1.f + expf(-logit));
    }
    __syncthreads();

    if (wid == 0) {
        float v = slog[lane];
        #pragma unroll
        for (int o = 16; o > 0; o >>= 1) v += __shfl_down_sync(0xffffffffu, v, o);
        if (lane == 0) out[bn] = v * (1.0f / QLEN);
    }
}

// ---------------------------------------------------------------------------
// Input order: embeds, filters, lin_w, lin_b, question, doc1, doc2,
//              doc1_sim, doc2_sim
extern "C" void kernel_launch(void* const* d_in, const int* in_sizes, int n_in,
                              void* d_out, int out_size) {
    const float* embeds   = (const float*)d_in[0];
    const float* filters  = (const float*)d_in[1];
    const float* lin_w    = (const float*)d_in[2];
    const float* lin_b    = (const float*)d_in[3];
    const int*   question = (const int*)d_in[4];
    const int*   doc1     = (const int*)d_in[5];
    const int*   doc2     = (const int*)d_in[6];
    const float* doc1_sim = (const float*)d_in[7];
    const float* doc2_sim = (const float*)d_in[8];
    float* out = (float*)d_out;

    cudaFuncSetAttribute(k_doc, cudaFuncAttributeMaxDynamicSharedMemorySize, DOC_SMEM);

    k_prep_q<<<QLEN, 128>>>(embeds, question);
    k_qconv<<<dim3(QLEN, 3), 128>>>(filters);
    k_buildU<<<dim3(96, 3), 128>>>(filters);

    k_doc<<<2 * NSENT, 256, DOC_SMEM>>>(embeds, filters, doc1, doc2,
                                        doc1_sim, doc2_sim, question,
                                        lin_w, lin_b, out);
}

// round 13
// speedup vs baseline: 3.2437x; 1.3433x over previous
#include <cuda_runtime.h>
#include <cuda_bf16.h>
#include <math.h>
#include <stdint.h>

#define NV 50000
#define NE 300
#define NF 300
#define NSENT 1024
#define SLEN 128
#define QLEN 32

// Device-global scratch — ~231KB (guard-safe, verified passing R9/R10/R12).
// g_B2t layout: [c][304] row-major fp32 (c: 0..31 = q_emb cols, 32+32k+q = U_k[q]).
__device__ float g_B2t[128 * 304];
__device__ float g_qemb[QLEN * NE];
__device__ float g_qconv[QLEN * NF];
__device__ float g_invq[64];         // [0..31]=1/|q_emb|, [32..63]=1/|q_conv|

// ---------------------------------------------------------------------------
__device__ __forceinline__ uint32_t smem_u32(const void* p) {
    return (uint32_t)__cvta_generic_to_shared(p);
}

#define LDSM_X4(r0, r1, r2, r3, a) \
    asm volatile("ldmatrix.sync.aligned.m8n8.x4.shared.b16 {%0,%1,%2,%3}, [%4];" \
                 : "=r"(r0), "=r"(r1), "=r"(r2), "=r"(r3) : "r"(a))

#define MMA16816(d, a0, a1, a2, a3, b0, b1) \
    asm volatile("mma.sync.aligned.m16n8k16.row.col.f32.bf16.bf16.f32 " \
                 "{%0,%1,%2,%3}, {%4,%5,%6,%7}, {%8,%9}, {%0,%1,%2,%3};" \
                 : "+f"((d)[0]), "+f"((d)[1]), "+f"((d)[2]), "+f"((d)[3]) \
                 : "r"(a0), "r"(a1), "r"(a2), "r"(a3), "r"(b0), "r"(b1))

// pack 4 fp32 -> 4 bf16 (two bf16x2 words)
__device__ __forceinline__ uint2 pack_bf16x4(float4 v) {
    __nv_bfloat162 lo = __floats2bfloat162_rn(v.x, v.y);
    __nv_bfloat162 hi = __floats2bfloat162_rn(v.z, v.w);
    uint2 r;
    r.x = *(uint32_t*)&lo;
    r.y = *(uint32_t*)&hi;
    return r;
}

// ---------------------------------------------------------------------------
// Prep kernels
__global__ void k_prep_q(const float* __restrict__ embeds, const int* __restrict__ question) {
    int q = blockIdx.x;
    int tid = threadIdx.x;
    int tok = question[q];
    const float* src = embeds + (size_t)tok * NE;
    float ss = 0.f;
    for (int e = tid; e < NE; e += 128) {
        float v = src[e];
        g_qemb[q * NE + e] = v;
        g_B2t[q * 304 + e] = v;
        ss += v * v;
    }
    __shared__ float red[128];
    red[tid] = ss;
    __syncthreads();
    for (int o = 64; o > 0; o >>= 1) {
        if (tid < o) red[tid] += red[tid + o];
        __syncthreads();
    }
    if (tid == 0) g_invq[q] = rsqrtf(red[0]);
}

__global__ void k_qconv(const float* __restrict__ filters) {
    int q = blockIdx.x;
    int f = blockIdx.y * 128 + threadIdx.x;
    if (f >= NF) return;
    float acc = 0.f;
    for (int k = 0; k < 3; k++) {
        if (q + k >= QLEN) break;
        const float* w = filters + (size_t)f * 900 + k * 300;
        const float* x = g_qemb + (q + k) * NE;
        #pragma unroll 4
        for (int e = 0; e < NE; e++) acc += x[e] * w[e];
    }
    g_qconv[q * NF + f] = acc;
}

// buildU + folded qnorm; writes transposed row layout
__global__ void k_buildU(const float* __restrict__ filters) {
    __shared__ float red[128];
    int c = blockIdx.x;
    int k = c >> 5, q = c & 31;
    int e = blockIdx.y * 100 + threadIdx.x;
    if (threadIdx.x < 100) {
        const float* qc = g_qconv + q * NF;
        const float* fb = filters + k * 300 + e;
        float a0 = 0.f, a1 = 0.f, a2 = 0.f, a3 = 0.f;
        for (int f = 0; f < NF; f += 4) {
            a0 += fb[(size_t)(f + 0) * 900] * qc[f + 0];
            a1 += fb[(size_t)(f + 1) * 900] * qc[f + 1];
            a2 += fb[(size_t)(f + 2) * 900] * qc[f + 2];
            a3 += fb[(size_t)(f + 3) * 900] * qc[f + 3];
        }
        g_B2t[(32 + c) * 304 + e] = (a0 + a1) + (a2 + a3);
    }
    if (blockIdx.y == 0 && blockIdx.x < 32) {
        int qq = blockIdx.x;
        int tid = threadIdx.x;
        float ss = 0.f;
        for (int f = tid; f < NF; f += 128) {
            float v = g_qconv[qq * NF + f];
            ss += v * v;
        }
        red[tid] = ss;
        __syncthreads();
        for (int o = 64; o > 0; o >>= 1) {
            if (tid < o) red[tid] += red[tid + o];
            __syncthreads();
        }
        if (tid == 0) g_invq[32 + qq] = rsqrtf(red[0]);
    }
}

// ---------------------------------------------------------------------------
// top-5 over 4 register values per lane (128 values per warp)
__device__ __forceinline__ void top5v(float v0, float v1, float v2, float v3,
                                      int lane, float& mx, float& mean5) {
    float v[4] = {v0, v1, v2, v3};
    float summ = 0.f;
    mx = 0.f;
    #pragma unroll
    for (int r = 0; r < 5; r++) {
        float bv = v[0];
        int bj = 0;
        #pragma unroll
        for (int j = 1; j < 4; j++)
            if (v[j] > bv) { bv = v[j]; bj = j; }
        float cv = bv;
        int cid = (lane << 2) | bj;
        #pragma unroll
        for (int o = 16; o > 0; o >>= 1) {
            float ov = __shfl_down_sync(0xffffffffu, cv, o);
            int oi = __shfl_down_sync(0xffffffffu, cid, o);
            if (ov > cv || (ov == cv && oi < cid)) { cv = ov; cid = oi; }
        }
        cv = __shfl_sync(0xffffffffu, cv, 0);
        cid = __shfl_sync(0xffffffffu, cid, 0);
        summ += cv;
        if (r == 0) mx = cv;
        if ((cid >> 2) == lane) {
            #pragma unroll
            for (int j = 0; j < 4; j++)
                if ((cid & 3) == j) v[j] = -INFINITY;
        }
    }
    mean5 = summ * 0.2f;
}

// ---------------------------------------------------------------------------
// Fused per-sentence kernel (mma.sync), 103KB smem -> 2 CTAs/SM.
// All staging/gather loops vectorized: float4 LDG + bf16x2 cvt + STS.64.
#define EROW 312                  // bf16 row stride (624B: ldmatrix conflict-free)
#define ERN  130                  // 128 rows + 2 zero lookahead
#define OFF_E    0
#define SZ_E     (ERN * EROW * 2)          // 81120
#define OFF_W    SZ_E                      // 19968-byte staging slab (W / B2)
#define SZ_W     (32 * EROW * 2)
#define OFF_IDS  (OFF_W + SZ_W)            // 101088
#define OFF_INVI (OFF_IDS + 512)
#define OFF_INVS (OFF_INVI + 512)
#define OFF_QV   (OFF_INVS + 512)          // qinvI[32] qinvS[32] qmf[32] slog[32]
#define DOC_SMEM (OFF_QV + 512)            // 103136
#define PSTRIDE  132                       // P[c][s] fp32, aliases dead E region

__global__ void __launch_bounds__(256, 2) k_doc(const float* __restrict__ embeds,
                                                const float* __restrict__ filters,
                                                const int* __restrict__ doc1,
                                                const int* __restrict__ doc2,
                                                const float* __restrict__ dsim1,
                                                const float* __restrict__ dsim2,
                                                const int* __restrict__ question,
                                                const float* __restrict__ lin_w,
                                                const float* __restrict__ lin_b,
                                                float* __restrict__ out) {
    extern __shared__ unsigned char smem[];
    __nv_bfloat16* Eb = (__nv_bfloat16*)(smem + OFF_E);
    __nv_bfloat16* Ws = (__nv_bfloat16*)(smem + OFF_W);
    int*   ids    = (int*)(smem + OFF_IDS);
    float* invI_s = (float*)(smem + OFF_INVI);
    float* invS_s = (float*)(smem + OFF_INVS);
    float* qinvI  = (float*)(smem + OFF_QV);
    float* qinvS  = qinvI + 32;
    float* qmf    = qinvS + 32;
    float* slog   = qmf + 32;
    float* P      = (float*)(smem + OFF_E);   // alias: E dead before P written

    int bn = blockIdx.x;
    const int* doc = (bn < NSENT) ? doc1 : doc2;
    const float* dsim = (bn < NSENT) ? dsim1 : dsim2;
    int n = (bn < NSENT) ? bn : bn - NSENT;

    int tid = threadIdx.x, lane = tid & 31, wid = tid >> 5;
    int g2 = lane >> 2, c4 = lane & 3;
    int t8 = lane >> 3, rr = lane & 7;
    int arow = (t8 & 1) * 8 + rr;
    int acol = (t8 >> 1) * 8;
    int brow = (t8 >> 1) * 8 + rr;
    int bcol = (t8 & 1) * 8;
    int mbase = wid * 16;

    // ---- phase 0: zero E pad rows + tail cols, ids + q-side constants ----
    {
        uint32_t* z = (uint32_t*)(smem + OFF_E);
        for (int i = tid; i < SZ_E / 4; i += 256) z[i] = 0u;
    }
    if (tid < SLEN) ids[tid] = doc[(size_t)n * SLEN + tid];
    if (tid < QLEN) {
        qmf[tid] = (question[tid] > 1) ? 1.f : 0.f;
        qinvI[tid] = g_invq[tid];
        qinvS[tid] = g_invq[32 + tid];
    }
    __syncthreads();

    // ---- phase 1: gather E -> bf16 (vectorized) + invI ----
    for (int s = wid; s < SLEN; s += 8) {
        const float4* row = (const float4*)(embeds + (size_t)ids[s] * NE);
        float ss = 0.f;
        for (int e4 = lane; e4 < 75; e4 += 32) {        // 75 float4 = 300 floats
            float4 v = row[e4];
            *(uint2*)&Eb[s * EROW + e4 * 4] = pack_bf16x4(v);
            ss += v.x * v.x + v.y * v.y + v.z * v.z + v.w * v.w;
        }
        #pragma unroll
        for (int o = 16; o > 0; o >>= 1) ss += __shfl_down_sync(0xffffffffu, ss, o);
        if (lane == 0) invI_s[s] = rsqrtf(ss);
    }

    uint32_t eh_u = smem_u32(Eb);
    uint32_t ws_u = smem_u32(Ws);

    // ---- phase 2: conv norms. 10 f-slabs; 3 taps accumulated per slab ----
    float rs0 = 0.f, rs1 = 0.f;
    for (int slab = 0; slab < 10; slab++) {
        float cc[4][4];
        #pragma unroll
        for (int j = 0; j < 4; j++)
            #pragma unroll
            for (int x = 0; x < 4; x++) cc[j][x] = 0.f;

        for (int tap = 0; tap < 3; tap++) {
            __syncthreads();
            // stage W(slab, tap): [32 f x 300 e] bf16, vectorized float4
            for (int i = tid; i < 32 * 76; i += 256) {
                int fl = i / 76, e4 = i - fl * 76;
                int f = slab * 32 + fl;
                float4 v = make_float4(0.f, 0.f, 0.f, 0.f);
                if (e4 < 75 && f < NF)
                    v = *(const float4*)(filters + (size_t)f * 900 + tap * 300 + e4 * 4);
                *(uint2*)&Ws[fl * EROW + e4 * 4] = pack_bf16x4(v);
            }
            __syncthreads();
            for (int ec = 0; ec < 19; ec++) {
                uint32_t a0, a1, a2, a3;
                uint32_t aaddr = eh_u + (uint32_t)(((mbase + tap + arow) * EROW + ec * 16 + acol) * 2);
                LDSM_X4(a0, a1, a2, a3, aaddr);
                #pragma unroll
                for (int np = 0; np < 2; np++) {
                    uint32_t b0, b1, b2, b3;
                    uint32_t baddr = ws_u + (uint32_t)(((np * 16 + brow) * EROW + ec * 16 + bcol) * 2);
                    LDSM_X4(b0, b1, b2, b3, baddr);
                    MMA16816(cc[np * 2], a0, a1, a2, a3, b0, b1);
                    MMA16816(cc[np * 2 + 1], a0, a1, a2, a3, b2, b3);
                }
            }
        }
        #pragma unroll
        for (int j = 0; j < 4; j++) {
            rs0 += cc[j][0] * cc[j][0] + cc[j][1] * cc[j][1];
            rs1 += cc[j][2] * cc[j][2] + cc[j][3] * cc[j][3];
        }
    }
    rs0 += __shfl_xor_sync(0xffffffffu, rs0, 1);
    rs0 += __shfl_xor_sync(0xffffffffu, rs0, 2);
    rs1 += __shfl_xor_sync(0xffffffffu, rs1, 1);
    rs1 += __shfl_xor_sync(0xffffffffu, rs1, 2);
    if (c4 == 0) {
        invS_s[mbase + g2] = rsqrtf(rs0);
        invS_s[mbase + g2 + 8] = rsqrtf(rs1);
    }

    // ---- phase 3: P = E @ B2t, single-pass bf16, 4 c-slabs of 32 ----
    float pa[4][4][4];
    #pragma unroll
    for (int cs = 0; cs < 4; cs++)
        #pragma unroll
        for (int nt = 0; nt < 4; nt++)
            #pragma unroll
            for (int x = 0; x < 4; x++) pa[cs][nt][x] = 0.f;

    for (int cs = 0; cs < 4; cs++) {
        __syncthreads();
        // stage B2t rows [cs*32 .. cs*32+31] (vectorized; rows are contiguous)
        for (int i = tid; i < 32 * 76; i += 256) {
            int cl = i / 76, e4 = i - cl * 76;
            float4 v = make_float4(0.f, 0.f, 0.f, 0.f);
            if (e4 < 75)
                v = *(const float4*)(g_B2t + (size_t)(cs * 32 + cl) * 304 + e4 * 4);
            *(uint2*)&Ws[cl * EROW + e4 * 4] = pack_bf16x4(v);
        }
        __syncthreads();
        for (int ec = 0; ec < 19; ec++) {
            uint32_t a0, a1, a2, a3;
            uint32_t aaddr = eh_u + (uint32_t)(((mbase + arow) * EROW + ec * 16 + acol) * 2);
            LDSM_X4(a0, a1, a2, a3, aaddr);
            #pragma unroll
            for (int np = 0; np < 2; np++) {
                uint32_t b0, b1, b2, b3;
                uint32_t baddr = ws_u + (uint32_t)(((np * 16 + brow) * EROW + ec * 16 + bcol) * 2);
                LDSM_X4(b0, b1, b2, b3, baddr);
                MMA16816(pa[cs][np * 2], a0, a1, a2, a3, b0, b1);
                MMA16816(pa[cs][np * 2 + 1], a0, a1, a2, a3, b2, b3);
            }
        }
    }
    __syncthreads();   // all E reads done; safe to overwrite with P

    // store P[c][s] from fragments
    #pragma unroll
    for (int cs = 0; cs < 4; cs++)
        #pragma unroll
        for (int nt = 0; nt < 4; nt++) {
            int c = cs * 32 + nt * 8 + c4 * 2;
            int s = mbase + g2;
            P[c * PSTRIDE + s] = pa[cs][nt][0];
            P[(c + 1) * PSTRIDE + s] = pa[cs][nt][1];
            P[c * PSTRIDE + s + 8] = pa[cs][nt][2];
            P[(c + 1) * PSTRIDE + s + 8] = pa[cs][nt][3];
        }
    __syncthreads();

    // ---- phase 4/5: sims on the fly -> top-5 -> logit -> score ----
    float w0 = lin_w[0], w1 = lin_w[1], w2 = lin_w[2];
    float w3 = lin_w[3], w4 = lin_w[4], w5 = lin_w[5], b0 = lin_b[0];
    for (int qq = wid * 4; qq < wid * 4 + 4; qq++) {
        float qi = qinvI[qq], qs = qinvS[qq], qm = qmf[qq];
        float vI[4], vS[4], vO[4];
        #pragma unroll
        for (int j = 0; j < 4; j++) {
            int s = lane + 32 * j;
            float a = P[qq * PSTRIDE + s] * qi * invI_s[s] * qm;
            if (ids[s] <= 1) a = 0.f;
            vI[j] = a;
            float num = P[(32 + qq) * PSTRIDE + s];
            if (s + 1 < SLEN) num += P[(64 + qq) * PSTRIDE + s + 1];
            if (s + 2 < SLEN) num += P[(96 + qq) * PSTRIDE + s + 2];
            vS[j] = num * qs * invS_s[s];
            vO[j] = dsim[((size_t)n * QLEN + qq) * SLEN + s];
        }
        float mI, aI, mS, aS, mO, aO;
        top5v(vI[0], vI[1], vI[2], vI[3], lane, mI, aI);
        top5v(vS[0], vS[1], vS[2], vS[3], lane, mS, aS);
        top5v(vO[0], vO[1], vO[2], vO[3], lane, mO, aO);
        float logit = b0 + w0 * mI + w1 * aI + w2 * mS + w3 * aS + w4 * mO + w5 * aO;
        if (lane == 0) slog[qq] = 1.f / (1.f + expf(-logit));
    }
    __syncthreads();

    if (wid == 0) {
        float v = slog[lane];
        #pragma unroll
        for (int o = 16; o > 0; o >>= 1) v += __shfl_down_sync(0xffffffffu, v, o);
        if (lane == 0) out[bn] = v * (1.0f / QLEN);
    }
}

// ---------------------------------------------------------------------------
// Input order: embeds, filters, lin_w, lin_b, question, doc1, doc2,
//              doc1_sim, doc2_sim
extern "C" void kernel_launch(void* const* d_in, const int* in_sizes, int n_in,
                              void* d_out, int out_size) {
    const float* embeds   = (const float*)d_in[0];
    const float* filters  = (const float*)d_in[1];
    const float* lin_w    = (const float*)d_in[2];
    const float* lin_b    = (const float*)d_in[3];
    const int*   question = (const int*)d_in[4];
    const int*   doc1     = (const int*)d_in[5];
    const int*   doc2     = (const int*)d_in[6];
    const float* doc1_sim = (const float*)d_in[7];
    const float* doc2_sim = (const float*)d_in[8];
    float* out = (float*)d_out;

    cudaFuncSetAttribute(k_doc, cudaFuncAttributeMaxDynamicSharedMemorySize, DOC_SMEM);

    k_prep_q<<<QLEN, 128>>>(embeds, question);
    k_qconv<<<dim3(QLEN, 3), 128>>>(filters);
    k_buildU<<<dim3(96, 3), 128>>>(filters);

    k_doc<<<2 * NSENT, 256, DOC_SMEM>>>(embeds, filters, doc1, doc2,
                                        doc1_sim, doc2_sim, question,
                                        lin_w, lin_b, out);
}